// round 2
// baseline (speedup 1.0000x reference)
#include <cuda_runtime.h>
#include <cstdint>
#include <cstddef>

#define N_NODES 50000
#define N_EDGES 600000
#define FDIM    128
#define ADIM    64
#define HID     512

// Scratch: aggregated conv output h[N, F]
__device__ float g_h[(size_t)N_NODES * FDIM];
// Flag: 1 if edge_index is stored as int64, 0 if int32
__device__ int g_is64;

// ---------------------------------------------------------------------------
// Probe edge_index dtype: read first 8 entries as int64; if all are valid
// node indices the buffer really is int64, otherwise it is int32.
// ---------------------------------------------------------------------------
__global__ void k_probe(const void* ei) {
    const long long* p = (const long long*)ei;
    int ok = 1;
    #pragma unroll
    for (int i = 0; i < 8; i++) {
        long long v = p[i];
        if (v < 0 || v >= N_NODES) ok = 0;
    }
    g_is64 = ok;
}

// ---------------------------------------------------------------------------
// Zero the scratch accumulator
// ---------------------------------------------------------------------------
__global__ void k_zero() {
    float4* p4 = reinterpret_cast<float4*>(g_h);
    const int n4 = N_NODES * FDIM / 4;
    float4 z = make_float4(0.f, 0.f, 0.f, 0.f);
    for (int i = blockIdx.x * blockDim.x + threadIdx.x; i < n4;
         i += gridDim.x * blockDim.x)
        p4[i] = z;
}

// ---------------------------------------------------------------------------
// Edge kernel: per-edge kernel = attr @ W, msg = x[src] * kernel,
// scatter-add into g_h[tgt] with vectorized red.global.add.v4.f32
// Block = 256 threads (8 warps). Each warp handles 4 edges of a 32-edge tile.
// ---------------------------------------------------------------------------
__global__ __launch_bounds__(256) void k_edge(
    const float* __restrict__ x,
    const float* __restrict__ attr,
    const void* __restrict__ ei,
    const float* __restrict__ kW)
{
    __shared__ float Wsh[ADIM * FDIM];     // 32 KB
    __shared__ float attrT[ADIM * 33];     // [a][edge], stride 33 -> bank-free
    __shared__ int ssrc[32];
    __shared__ int stgt[32];

    const int tid  = threadIdx.x;
    const int lane = tid & 31;
    const int wid  = tid >> 5;
    const int is64 = g_is64;
    const long long* ei64 = (const long long*)ei;
    const int*       ei32 = (const int*)ei;

    // Load kernel_W once per block
    for (int i = tid; i < ADIM * FDIM; i += 256) Wsh[i] = kW[i];

    const float4* W4 = reinterpret_cast<const float4*>(Wsh);
    const int ntiles = N_EDGES / 32;   // 18750, exact

    for (int tile = blockIdx.x; tile < ntiles; tile += gridDim.x) {
        const int e0 = tile * 32;
        __syncthreads();  // W ready (1st iter) / prev-tile consumers done

        if (tid < 32) {
            ssrc[tid] = is64 ? (int)ei64[e0 + tid] : ei32[e0 + tid];
        } else if (tid < 64) {
            int t = tid - 32;
            stgt[t] = is64 ? (int)ei64[N_EDGES + e0 + t]
                           : ei32[N_EDGES + e0 + t];
        }

        // Stage attr transposed: attrT[a][el], coalesced global reads
        #pragma unroll
        for (int r = 0; r < 8; r++) {
            int idx = tid + 256 * r;          // 0..2047
            int a  = idx & 63;
            int el = idx >> 6;
            attrT[a * 33 + el] = attr[(size_t)(e0 + el) * ADIM + a];
        }
        __syncthreads();

        const int el0 = wid * 4;
        float acc[4][4];
        #pragma unroll
        for (int e = 0; e < 4; e++)
            #pragma unroll
            for (int j = 0; j < 4; j++) acc[e][j] = 0.f;

        #pragma unroll 8
        for (int a = 0; a < ADIM; a++) {
            float4 wv = W4[a * 32 + lane];
            #pragma unroll
            for (int e = 0; e < 4; e++) {
                float av = attrT[a * 33 + el0 + e];   // smem broadcast
                acc[e][0] += av * wv.x;
                acc[e][1] += av * wv.y;
                acc[e][2] += av * wv.z;
                acc[e][3] += av * wv.w;
            }
        }

        #pragma unroll
        for (int e = 0; e < 4; e++) {
            const int src = ssrc[el0 + e];
            const int tgt = stgt[el0 + e];
            float4 xv = __ldg(reinterpret_cast<const float4*>(
                                  x + (size_t)src * FDIM) + lane);
            float m0 = acc[e][0] * xv.x;
            float m1 = acc[e][1] * xv.y;
            float m2 = acc[e][2] * xv.z;
            float m3 = acc[e][3] * xv.w;
            float* dst = g_h + (size_t)tgt * FDIM + lane * 4;
            asm volatile("red.global.add.v4.f32 [%0], {%1,%2,%3,%4};"
                         :: "l"(dst), "f"(m0), "f"(m1), "f"(m2), "f"(m3)
                         : "memory");
        }
    }
}

// ---------------------------------------------------------------------------
// Fused: +conv_bias, LayerNorm, MLP (128->512 GELU ->128), layer_scale,
// residual. Block = 256 threads handles 32 rows. Warp w owns rows w*4..w*4+3.
// W1/W2 staged through smem in 32-k tiles.
// ---------------------------------------------------------------------------
__device__ __forceinline__ float gelu_exact(float v) {
    return 0.5f * v * (1.0f + erff(v * 0.70710678118654752f));
}

__global__ __launch_bounds__(256) void k_mlp(
    const float* __restrict__ x,
    const float* __restrict__ cb,
    const float* __restrict__ gamma,
    const float* __restrict__ beta,
    const float* __restrict__ W1,
    const float* __restrict__ b1,
    const float* __restrict__ W2,
    const float* __restrict__ b2,
    const float* __restrict__ ls,
    float* __restrict__ out)
{
    __shared__ float htile[32 * 128];   // 16 KB  (post-LN activations)
    __shared__ float hid  [32 * 128];   // 16 KB  (current hidden chunk)
    __shared__ float wst  [32 * 128];   // 16 KB  (weight k-tile stage)

    const int tid  = threadIdx.x;
    const int lane = tid & 31;
    const int wid  = tid >> 5;
    const int row0 = blockIdx.x * 32;
    const int mbase = wid * 4;

    // ---- load h tile (+conv_bias) ----
    const float4* gh4 = reinterpret_cast<const float4*>(g_h);
    float4* ht4 = reinterpret_cast<float4*>(htile);
    #pragma unroll
    for (int r = 0; r < 4; r++) {
        int idx = tid + 256 * r;      // 0..1023 float4 slots
        int m  = idx >> 5;
        int c4 = idx & 31;
        int row = row0 + m;
        float4 v = make_float4(0.f, 0.f, 0.f, 0.f);
        if (row < N_NODES) {
            v = gh4[(size_t)row * 32 + c4];
            float4 cbv = __ldg(reinterpret_cast<const float4*>(cb) + c4);
            v.x += cbv.x; v.y += cbv.y; v.z += cbv.z; v.w += cbv.w;
        }
        ht4[m * 32 + c4] = v;
    }
    __syncthreads();

    // ---- LayerNorm: warp handles its 4 rows ----
    #pragma unroll
    for (int rr = 0; rr < 4; rr++) {
        int m = mbase + rr;
        float v0 = htile[m * 128 + lane];
        float v1 = htile[m * 128 + lane + 32];
        float v2 = htile[m * 128 + lane + 64];
        float v3 = htile[m * 128 + lane + 96];
        float s1 = v0 + v1 + v2 + v3;
        float s2 = v0 * v0 + v1 * v1 + v2 * v2 + v3 * v3;
        #pragma unroll
        for (int o = 16; o > 0; o >>= 1) {
            s1 += __shfl_xor_sync(0xffffffffu, s1, o);
            s2 += __shfl_xor_sync(0xffffffffu, s2, o);
        }
        float mu   = s1 * (1.0f / 128.0f);
        float var  = s2 * (1.0f / 128.0f) - mu * mu;
        float rstd = rsqrtf(var + 1e-5f);
        htile[m * 128 + lane]      = (v0 - mu) * rstd * __ldg(gamma + lane)      + __ldg(beta + lane);
        htile[m * 128 + lane + 32] = (v1 - mu) * rstd * __ldg(gamma + lane + 32) + __ldg(beta + lane + 32);
        htile[m * 128 + lane + 64] = (v2 - mu) * rstd * __ldg(gamma + lane + 64) + __ldg(beta + lane + 64);
        htile[m * 128 + lane + 96] = (v3 - mu) * rstd * __ldg(gamma + lane + 96) + __ldg(beta + lane + 96);
    }
    // (guarded by the first staging __syncthreads below)

    const float4* W1_4 = reinterpret_cast<const float4*>(W1);
    const float4* W2_4 = reinterpret_cast<const float4*>(W2);
    float4* wst4 = reinterpret_cast<float4*>(wst);
    float4* hid4 = reinterpret_cast<float4*>(hid);

    float outacc[4][4];
    #pragma unroll
    for (int mm = 0; mm < 4; mm++)
        #pragma unroll
        for (int j = 0; j < 4; j++) outacc[mm][j] = 0.f;

    for (int jc = 0; jc < 4; jc++) {          // hidden chunks of 128
        float h1[4][4];
        #pragma unroll
        for (int mm = 0; mm < 4; mm++)
            #pragma unroll
            for (int j = 0; j < 4; j++) h1[mm][j] = 0.f;

        // ---- GEMM1: h1 = htile @ W1[:, jc*128 : jc*128+128] ----
        for (int kt = 0; kt < 4; kt++) {
            __syncthreads();
            #pragma unroll
            for (int r = 0; r < 4; r++) {
                int idx = tid + 256 * r;
                int kr = idx >> 5, c4 = idx & 31;
                wst4[kr * 32 + c4] =
                    W1_4[(size_t)(kt * 32 + kr) * 128 + jc * 32 + c4];
            }
            __syncthreads();
            #pragma unroll 8
            for (int k = 0; k < 32; k++) {
                float4 w = wst4[k * 32 + lane];
                #pragma unroll
                for (int mm = 0; mm < 4; mm++) {
                    float hm = htile[(mbase + mm) * 128 + kt * 32 + k];
                    h1[mm][0] += hm * w.x;
                    h1[mm][1] += hm * w.y;
                    h1[mm][2] += hm * w.z;
                    h1[mm][3] += hm * w.w;
                }
            }
        }

        // ---- bias + exact GELU, park in smem (same-warp rows only) ----
        #pragma unroll
        for (int mm = 0; mm < 4; mm++) {
            int jb = jc * 128 + lane * 4;
            float4 hv;
            hv.x = gelu_exact(h1[mm][0] + __ldg(b1 + jb + 0));
            hv.y = gelu_exact(h1[mm][1] + __ldg(b1 + jb + 1));
            hv.z = gelu_exact(h1[mm][2] + __ldg(b1 + jb + 2));
            hv.w = gelu_exact(h1[mm][3] + __ldg(b1 + jb + 3));
            hid4[(mbase + mm) * 32 + lane] = hv;
        }

        // ---- GEMM2: outacc += hid @ W2[jc*128 : jc*128+128, :] ----
        for (int kkt = 0; kkt < 4; kkt++) {
            __syncthreads();
            #pragma unroll
            for (int r = 0; r < 4; r++) {
                int idx = tid + 256 * r;
                int kr = idx >> 5, c4 = idx & 31;
                wst4[kr * 32 + c4] =
                    W2_4[(size_t)(jc * 128 + kkt * 32 + kr) * 32 + c4];
            }
            __syncthreads();
            #pragma unroll 8
            for (int kk = 0; kk < 32; kk++) {
                float4 w = wst4[kk * 32 + lane];
                #pragma unroll
                for (int mm = 0; mm < 4; mm++) {
                    float hm = hid[(mbase + mm) * 128 + kkt * 32 + kk];
                    outacc[mm][0] += hm * w.x;
                    outacc[mm][1] += hm * w.y;
                    outacc[mm][2] += hm * w.z;
                    outacc[mm][3] += hm * w.w;
                }
            }
        }
    }

    // ---- epilogue: out = x + ls * (outacc + b2) ----
    float4 b2v = __ldg(reinterpret_cast<const float4*>(b2) + lane);
    float4 lsv = __ldg(reinterpret_cast<const float4*>(ls) + lane);
    #pragma unroll
    for (int mm = 0; mm < 4; mm++) {
        int row = row0 + mbase + mm;
        if (row < N_NODES) {
            float4 xv = __ldg(reinterpret_cast<const float4*>(
                                  x + (size_t)row * FDIM) + lane);
            float4 o;
            o.x = xv.x + lsv.x * (outacc[mm][0] + b2v.x);
            o.y = xv.y + lsv.y * (outacc[mm][1] + b2v.y);
            o.z = xv.z + lsv.z * (outacc[mm][2] + b2v.z);
            o.w = xv.w + lsv.w * (outacc[mm][3] + b2v.w);
            reinterpret_cast<float4*>(out + (size_t)row * FDIM)[lane] = o;
        }
    }
}

// ---------------------------------------------------------------------------
extern "C" void kernel_launch(void* const* d_in, const int* in_sizes, int n_in,
                              void* d_out, int out_size)
{
    const float* x     = (const float*)d_in[0];
    const float* attr  = (const float*)d_in[1];
    const void*  ei    = d_in[2];
    // d_in[3] = batch (unused)
    const float* kW    = (const float*)d_in[4];
    const float* cb    = (const float*)d_in[5];
    const float* gamma = (const float*)d_in[6];
    const float* beta  = (const float*)d_in[7];
    const float* W1    = (const float*)d_in[8];
    const float* b1    = (const float*)d_in[9];
    const float* W2    = (const float*)d_in[10];
    const float* b2    = (const float*)d_in[11];
    const float* ls    = (const float*)d_in[12];
    float*       out   = (float*)d_out;

    k_probe<<<1, 1>>>(ei);
    k_zero<<<1024, 256>>>();
    k_edge<<<740, 256>>>(x, attr, ei, kW);
    k_mlp<<<(N_NODES + 31) / 32, 256>>>(x, cb, gamma, beta,
                                        W1, b1, W2, b2, ls, out);
}

// round 4
// speedup vs baseline: 1.8052x; 1.8052x over previous
#include <cuda_runtime.h>
#include <cuda_bf16.h>
#include <cstdint>
#include <cstddef>

#define N_NODES 50000
#define N_EDGES 600000
#define FDIM    128
#define ADIM    64
#define HID     512
#define PAD     136   // bf16 elems per smem row: 272B stride -> conflict-free ldmatrix

// Scratch
__device__ float g_h[(size_t)N_NODES * FDIM];
__device__ __nv_bfloat16 g_W1b[FDIM * HID];
__device__ __nv_bfloat16 g_W2b[HID * FDIM];
__device__ int g_is64;

// ---------------------------------------------------------------------------
__global__ void k_probe(const void* ei) {
    const long long* p = (const long long*)ei;
    int ok = 1;
    #pragma unroll
    for (int i = 0; i < 8; i++) {
        long long v = p[i];
        if (v < 0 || v >= N_NODES) ok = 0;
    }
    g_is64 = ok;
}

__global__ void k_zero() {
    float4* p4 = reinterpret_cast<float4*>(g_h);
    const int n4 = N_NODES * FDIM / 4;
    float4 z = make_float4(0.f, 0.f, 0.f, 0.f);
    for (int i = blockIdx.x * blockDim.x + threadIdx.x; i < n4;
         i += gridDim.x * blockDim.x)
        p4[i] = z;
}

__global__ void k_cvt(const float* __restrict__ W1, const float* __restrict__ W2) {
    int i = blockIdx.x * 256 + threadIdx.x;     // grid 512 -> 131072 threads
    if (i < FDIM * HID) g_W1b[i] = __float2bfloat16(W1[i]);
    else                g_W2b[i - FDIM * HID] = __float2bfloat16(W2[i - FDIM * HID]);
}

// ---------------------------------------------------------------------------
// Edge kernel: 64-edge tiles, 8 warps x 8 edges, vector RED scatter.
// ---------------------------------------------------------------------------
extern __shared__ __align__(16) char dsm_raw[];

__global__ __launch_bounds__(256) void k_edge(
    const float* __restrict__ x,
    const float* __restrict__ attr,
    const void* __restrict__ ei,
    const float* __restrict__ kW)
{
    float* Wsh   = reinterpret_cast<float*>(dsm_raw);        // 8192 floats (32KB)
    float* attrT = Wsh + ADIM * FDIM;                        // [64][65] (16.6KB)

    const int tid  = threadIdx.x;
    const int lane = tid & 31;
    const int wid  = tid >> 5;
    const int is64 = g_is64;
    const long long* ei64 = (const long long*)ei;
    const int*       ei32 = (const int*)ei;

    for (int i = tid; i < ADIM * FDIM; i += 256) Wsh[i] = kW[i];

    const float4* W4 = reinterpret_cast<const float4*>(Wsh);
    const int ntiles = N_EDGES / 64;   // 9375, exact

    for (int tile = blockIdx.x; tile < ntiles; tile += gridDim.x) {
        const int e0 = tile * 64;
        __syncthreads();   // W ready / previous tile consumers done

        // Stage attr transposed: attrT[a][el]
        #pragma unroll
        for (int r = 0; r < 16; r++) {
            int idx = tid + 256 * r;          // 0..4095
            int a  = idx & 63;
            int el = idx >> 6;
            attrT[a * 65 + el] = attr[(size_t)(e0 + el) * ADIM + a];
        }
        __syncthreads();

        const int el0 = wid * 8;
        float acc[8][4];
        #pragma unroll
        for (int e = 0; e < 8; e++)
            #pragma unroll
            for (int j = 0; j < 4; j++) acc[e][j] = 0.f;

        #pragma unroll 4
        for (int a = 0; a < ADIM; a++) {
            float4 wv = W4[a * 32 + lane];
            #pragma unroll
            for (int e = 0; e < 8; e++) {
                float av = attrT[a * 65 + el0 + e];   // smem broadcast
                acc[e][0] += av * wv.x;
                acc[e][1] += av * wv.y;
                acc[e][2] += av * wv.z;
                acc[e][3] += av * wv.w;
            }
        }

        #pragma unroll
        for (int e = 0; e < 8; e++) {
            const int eg  = e0 + el0 + e;
            const int src = is64 ? (int)ei64[eg] : ei32[eg];
            const int tgt = is64 ? (int)ei64[N_EDGES + eg] : ei32[N_EDGES + eg];
            float4 xv = __ldg(reinterpret_cast<const float4*>(
                                  x + (size_t)src * FDIM) + lane);
            float m0 = acc[e][0] * xv.x;
            float m1 = acc[e][1] * xv.y;
            float m2 = acc[e][2] * xv.z;
            float m3 = acc[e][3] * xv.w;
            float* dst = g_h + (size_t)tgt * FDIM + lane * 4;
            asm volatile("red.global.add.v4.f32 [%0], {%1,%2,%3,%4};"
                         :: "l"(dst), "f"(m0), "f"(m1), "f"(m2), "f"(m3)
                         : "memory");
        }
    }
}

// ---------------------------------------------------------------------------
// Tensor-core MLP: LN(fp32) -> bf16 mma GEMM1 -> GELU -> bf16 mma GEMM2 ->
// layer_scale + residual. Block = 256 threads, 64 rows. Warp (wr,wc) owns a
// 16x64 output tile. Hidden processed in 4 chunks of 128.
// ---------------------------------------------------------------------------
__device__ __forceinline__ float gelu_exact(float v) {
    return 0.5f * v * (1.0f + erff(v * 0.70710678118654752f));
}
__device__ __forceinline__ uint32_t smem_u32(const void* p) {
    return (uint32_t)__cvta_generic_to_shared(p);
}
__device__ __forceinline__ void ldsm_x4(uint32_t& r0, uint32_t& r1,
                                        uint32_t& r2, uint32_t& r3, uint32_t a) {
    asm volatile("ldmatrix.sync.aligned.m8n8.x4.shared.b16 {%0,%1,%2,%3}, [%4];"
                 : "=r"(r0), "=r"(r1), "=r"(r2), "=r"(r3) : "r"(a));
}
__device__ __forceinline__ void ldsm_x4_t(uint32_t& r0, uint32_t& r1,
                                          uint32_t& r2, uint32_t& r3, uint32_t a) {
    asm volatile("ldmatrix.sync.aligned.m8n8.x4.trans.shared.b16 {%0,%1,%2,%3}, [%4];"
                 : "=r"(r0), "=r"(r1), "=r"(r2), "=r"(r3) : "r"(a));
}
__device__ __forceinline__ void mma16816(float* d, const uint32_t* a,
                                         const uint32_t* b) {
    asm volatile(
        "mma.sync.aligned.m16n8k16.row.col.f32.bf16.bf16.f32 "
        "{%0,%1,%2,%3}, {%4,%5,%6,%7}, {%8,%9}, {%0,%1,%2,%3};"
        : "+f"(d[0]), "+f"(d[1]), "+f"(d[2]), "+f"(d[3])
        : "r"(a[0]), "r"(a[1]), "r"(a[2]), "r"(a[3]), "r"(b[0]), "r"(b[1]));
}
__device__ __forceinline__ uint32_t pack_bf16(float lo, float hi) {
    return ((uint32_t)__bfloat16_as_ushort(__float2bfloat16(hi)) << 16) |
            (uint32_t)__bfloat16_as_ushort(__float2bfloat16(lo));
}

__global__ __launch_bounds__(256) void k_mlp(
    const float* __restrict__ x,
    const float* __restrict__ cb,
    const float* __restrict__ gamma,
    const float* __restrict__ beta,
    const float* __restrict__ b1,
    const float* __restrict__ b2,
    const float* __restrict__ ls,
    float* __restrict__ out)
{
    __nv_bfloat16* htile = reinterpret_cast<__nv_bfloat16*>(dsm_raw);  // [64][PAD]
    __nv_bfloat16* hid   = htile + 64 * PAD;                           // [64][PAD]
    __nv_bfloat16* wst   = htile + 128 * PAD;                          // [128][PAD]

    const int tid  = threadIdx.x;
    const int lane = tid & 31;
    const int wid  = tid >> 5;
    const int row0 = blockIdx.x * 64;
    const int wr   = wid & 3;          // 16-row slab
    const int wc   = wid >> 2;         // 64-col half

    // ---- LayerNorm (fp32) -> bf16 htile. Warp handles rows wid*8..+8 ----
    #pragma unroll
    for (int rr = 0; rr < 8; rr++) {
        int m = wid * 8 + rr;
        int row = row0 + m;
        if (row < N_NODES) {
            float v[4];
            #pragma unroll
            for (int q = 0; q < 4; q++)
                v[q] = g_h[(size_t)row * FDIM + lane + 32 * q]
                       + __ldg(cb + lane + 32 * q);
            float s1 = v[0] + v[1] + v[2] + v[3];
            float s2 = v[0]*v[0] + v[1]*v[1] + v[2]*v[2] + v[3]*v[3];
            #pragma unroll
            for (int o = 16; o > 0; o >>= 1) {
                s1 += __shfl_xor_sync(0xffffffffu, s1, o);
                s2 += __shfl_xor_sync(0xffffffffu, s2, o);
            }
            float mu   = s1 * (1.0f / 128.0f);
            float var  = s2 * (1.0f / 128.0f) - mu * mu;
            float rstd = rsqrtf(var + 1e-5f);
            #pragma unroll
            for (int q = 0; q < 4; q++) {
                float g = __ldg(gamma + lane + 32 * q);
                float b = __ldg(beta  + lane + 32 * q);
                htile[m * PAD + lane + 32 * q] =
                    __float2bfloat16((v[q] - mu) * rstd * g + b);
            }
        } else {
            #pragma unroll
            for (int q = 0; q < 4; q++)
                htile[m * PAD + lane + 32 * q] = __float2bfloat16(0.f);
        }
    }

    const uint32_t ht_b  = smem_u32(htile);
    const uint32_t hid_b = smem_u32(hid);
    const uint32_t w_b   = smem_u32(wst);

    float oacc[8][4];
    #pragma unroll
    for (int i = 0; i < 8; i++)
        #pragma unroll
        for (int j = 0; j < 4; j++) oacc[i][j] = 0.f;

    for (int jc = 0; jc < 4; jc++) {
        // ---- stage W1[:, jc*128:+128] (bf16) ----
        __syncthreads();   // htile ready (jc=0) / wst & hid consumers done
        {
            const uint4* g = reinterpret_cast<const uint4*>(g_W1b);
            #pragma unroll
            for (int r8 = 0; r8 < 8; r8++) {
                int idx = tid + 256 * r8;          // 0..2047
                int krow = idx >> 4, c8 = idx & 15;
                *reinterpret_cast<uint4*>(wst + krow * PAD + c8 * 8) =
                    g[krow * 64 + jc * 16 + c8];
            }
        }
        __syncthreads();

        // ---- GEMM1: g1[16x64] = htile[wr] @ W1chunk[:, wc*64:+64] ----
        float g1[8][4];
        #pragma unroll
        for (int i = 0; i < 8; i++)
            #pragma unroll
            for (int j = 0; j < 4; j++) g1[i][j] = 0.f;

        #pragma unroll
        for (int ks = 0; ks < 8; ks++) {
            int k0 = ks * 16;
            uint32_t a[4];
            ldsm_x4(a[0], a[1], a[2], a[3],
                    ht_b + ((wr * 16 + (lane & 15)) * PAD + k0 + (lane >> 4) * 8) * 2);
            #pragma unroll
            for (int ip = 0; ip < 4; ip++) {
                uint32_t b[4];
                ldsm_x4_t(b[0], b[1], b[2], b[3],
                          w_b + ((k0 + (lane & 15)) * PAD + wc * 64 + ip * 16
                                 + (lane >> 4) * 8) * 2);
                mma16816(g1[2 * ip],     a, b);
                mma16816(g1[2 * ip + 1], a, b + 2);
            }
        }

        // ---- bias + GELU -> bf16 hid ----
        {
            int rg = wr * 16 + (lane >> 2);
            #pragma unroll
            for (int i = 0; i < 8; i++) {
                int coln = wc * 64 + i * 8 + (lane & 3) * 2;
                float2 bv = __ldg(reinterpret_cast<const float2*>(
                                      b1 + jc * 128 + coln));
                uint32_t p0 = pack_bf16(gelu_exact(g1[i][0] + bv.x),
                                        gelu_exact(g1[i][1] + bv.y));
                uint32_t p1 = pack_bf16(gelu_exact(g1[i][2] + bv.x),
                                        gelu_exact(g1[i][3] + bv.y));
                *reinterpret_cast<uint32_t*>(hid + rg * PAD + coln) = p0;
                *reinterpret_cast<uint32_t*>(hid + (rg + 8) * PAD + coln) = p1;
            }
        }
        __syncthreads();   // hid complete (both col-half warps)

        // ---- stage W2[jc*128:+128, :] (bf16) ----
        {
            const uint4* g = reinterpret_cast<const uint4*>(g_W2b);
            #pragma unroll
            for (int r8 = 0; r8 < 8; r8++) {
                int idx = tid + 256 * r8;
                int krow = idx >> 4, c8 = idx & 15;
                *reinterpret_cast<uint4*>(wst + krow * PAD + c8 * 8) =
                    g[(jc * 128 + krow) * 16 + c8];
            }
        }
        __syncthreads();

        // ---- GEMM2: oacc += hid[wr] @ W2chunk[:, wc*64:+64] ----
        #pragma unroll
        for (int ks = 0; ks < 8; ks++) {
            int k0 = ks * 16;
            uint32_t a[4];
            ldsm_x4(a[0], a[1], a[2], a[3],
                    hid_b + ((wr * 16 + (lane & 15)) * PAD + k0 + (lane >> 4) * 8) * 2);
            #pragma unroll
            for (int ip = 0; ip < 4; ip++) {
                uint32_t b[4];
                ldsm_x4_t(b[0], b[1], b[2], b[3],
                          w_b + ((k0 + (lane & 15)) * PAD + wc * 64 + ip * 16
                                 + (lane >> 4) * 8) * 2);
                mma16816(oacc[2 * ip],     a, b);
                mma16816(oacc[2 * ip + 1], a, b + 2);
            }
        }
    }

    // ---- epilogue: out = x + ls * (oacc + b2) ----
    {
        int rg = row0 + wr * 16 + (lane >> 2);
        #pragma unroll
        for (int i = 0; i < 8; i++) {
            int coln = wc * 64 + i * 8 + (lane & 3) * 2;
            float2 b2v = __ldg(reinterpret_cast<const float2*>(b2 + coln));
            float2 lsv = __ldg(reinterpret_cast<const float2*>(ls + coln));
            if (rg < N_NODES) {
                float2 xv = *reinterpret_cast<const float2*>(
                                x + (size_t)rg * FDIM + coln);
                float2 o;
                o.x = xv.x + lsv.x * (oacc[i][0] + b2v.x);
                o.y = xv.y + lsv.y * (oacc[i][1] + b2v.y);
                *reinterpret_cast<float2*>(out + (size_t)rg * FDIM + coln) = o;
            }
            if (rg + 8 < N_NODES) {
                float2 xv = *reinterpret_cast<const float2*>(
                                x + (size_t)(rg + 8) * FDIM + coln);
                float2 o;
                o.x = xv.x + lsv.x * (oacc[i][2] + b2v.x);
                o.y = xv.y + lsv.y * (oacc[i][3] + b2v.y);
                *reinterpret_cast<float2*>(out + (size_t)(rg + 8) * FDIM + coln) = o;
            }
        }
    }
}

// ---------------------------------------------------------------------------
extern "C" void kernel_launch(void* const* d_in, const int* in_sizes, int n_in,
                              void* d_out, int out_size)
{
    const float* x     = (const float*)d_in[0];
    const float* attr  = (const float*)d_in[1];
    const void*  ei    = d_in[2];
    const float* kW    = (const float*)d_in[4];
    const float* cb    = (const float*)d_in[5];
    const float* gamma = (const float*)d_in[6];
    const float* beta  = (const float*)d_in[7];
    const float* W1    = (const float*)d_in[8];
    const float* b1    = (const float*)d_in[9];
    const float* W2    = (const float*)d_in[10];
    const float* b2    = (const float*)d_in[11];
    const float* ls    = (const float*)d_in[12];
    float*       out   = (float*)d_out;

    const int edge_smem = (ADIM * FDIM + ADIM * 65) * (int)sizeof(float);   // 49408
    const int mlp_smem  = (128 * PAD + 128 * PAD) * 2;                      // 69632
    cudaFuncSetAttribute(k_edge, cudaFuncAttributeMaxDynamicSharedMemorySize, edge_smem);
    cudaFuncSetAttribute(k_mlp,  cudaFuncAttributeMaxDynamicSharedMemorySize, mlp_smem);

    k_probe<<<1, 1>>>(ei);
    k_zero<<<1024, 256>>>();
    k_cvt<<<512, 256>>>(W1, W2);
    k_edge<<<740, 256, edge_smem>>>(x, attr, ei, kW);
    k_mlp<<<(N_NODES + 63) / 64, 256, mlp_smem>>>(x, cb, gamma, beta,
                                                  b1, b2, ls, out);
}

// round 6
// speedup vs baseline: 2.6803x; 1.4848x over previous
#include <cuda_runtime.h>
#include <cuda_bf16.h>
#include <cstdint>
#include <cstddef>

#define N_NODES 50000
#define N_EDGES 600000
#define FDIM    128
#define ADIM    64
#define HID     512
#define PAD     136   // bf16 row stride (272B) for 128-wide tiles -> ldmatrix conflict-free
#define PADA    72    // bf16 row stride (144B) for 64-wide attr tiles
#define ETILE   192   // edges per tile: 600000/192 = 3125 exact

// Scratch
__device__ float g_h[(size_t)N_NODES * FDIM];
__device__ __nv_bfloat16 g_W1b[FDIM * HID];
__device__ __nv_bfloat16 g_W2b[HID * FDIM];
__device__ __nv_bfloat16 g_Wkb[ADIM * FDIM];
__device__ int g_is64;

// ---------------------------------------------------------------------------
__global__ void k_probe(const void* ei) {
    const long long* p = (const long long*)ei;
    int ok = 1;
    #pragma unroll
    for (int i = 0; i < 8; i++) {
        long long v = p[i];
        if (v < 0 || v >= N_NODES) ok = 0;
    }
    g_is64 = ok;
}

__global__ void k_zero() {
    float4* p4 = reinterpret_cast<float4*>(g_h);
    const int n4 = N_NODES * FDIM / 4;
    float4 z = make_float4(0.f, 0.f, 0.f, 0.f);
    for (int i = blockIdx.x * blockDim.x + threadIdx.x; i < n4;
         i += gridDim.x * blockDim.x)
        p4[i] = z;
}

// Convert W1, W2, kernel_W to bf16. 544*256 = 139264 = 65536+65536+8192 exact.
__global__ void k_cvt(const float* __restrict__ W1, const float* __restrict__ W2,
                      const float* __restrict__ kW) {
    int i = blockIdx.x * 256 + threadIdx.x;
    if (i < FDIM * HID)          g_W1b[i] = __float2bfloat16(W1[i]);
    else if (i < 2 * FDIM * HID) g_W2b[i - FDIM * HID] = __float2bfloat16(W2[i - FDIM * HID]);
    else                         g_Wkb[i - 2 * FDIM * HID] = __float2bfloat16(kW[i - 2 * FDIM * HID]);
}

// ---------------------------------------------------------------------------
// mma helpers
// ---------------------------------------------------------------------------
__device__ __forceinline__ uint32_t smem_u32(const void* p) {
    return (uint32_t)__cvta_generic_to_shared(p);
}
__device__ __forceinline__ void ldsm_x4(uint32_t& r0, uint32_t& r1,
                                        uint32_t& r2, uint32_t& r3, uint32_t a) {
    asm volatile("ldmatrix.sync.aligned.m8n8.x4.shared.b16 {%0,%1,%2,%3}, [%4];"
                 : "=r"(r0), "=r"(r1), "=r"(r2), "=r"(r3) : "r"(a));
}
__device__ __forceinline__ void ldsm_x4_t(uint32_t& r0, uint32_t& r1,
                                          uint32_t& r2, uint32_t& r3, uint32_t a) {
    asm volatile("ldmatrix.sync.aligned.m8n8.x4.trans.shared.b16 {%0,%1,%2,%3}, [%4];"
                 : "=r"(r0), "=r"(r1), "=r"(r2), "=r"(r3) : "r"(a));
}
__device__ __forceinline__ void mma16816(float* d, const uint32_t* a,
                                         const uint32_t* b) {
    asm volatile(
        "mma.sync.aligned.m16n8k16.row.col.f32.bf16.bf16.f32 "
        "{%0,%1,%2,%3}, {%4,%5,%6,%7}, {%8,%9}, {%0,%1,%2,%3};"
        : "+f"(d[0]), "+f"(d[1]), "+f"(d[2]), "+f"(d[3])
        : "r"(a[0]), "r"(a[1]), "r"(a[2]), "r"(a[3]), "r"(b[0]), "r"(b[1]));
}
__device__ __forceinline__ uint32_t pack_bf16(float lo, float hi) {
    return ((uint32_t)__bfloat16_as_ushort(__float2bfloat16(hi)) << 16) |
            (uint32_t)__bfloat16_as_ushort(__float2bfloat16(lo));
}
__device__ __forceinline__ float gelu_exact(float v) {
    return 0.5f * v * (1.0f + erff(v * 0.70710678118654752f));
}

extern __shared__ __align__(16) char dsm_raw[];

// ---------------------------------------------------------------------------
// Edge kernel v2 (tensor cores): per 192-edge tile compute
// K[192,128] = bf16mma(attr[192,64], W[64,128]), then scatter
// g_h[tgt] += K[e] * x[src] with RED.v4.
// Block = 384 threads (12 warps); warp w owns edges w*16..+16, all 128 cols.
// ---------------------------------------------------------------------------
__global__ __launch_bounds__(384, 1) void k_edge(
    const float* __restrict__ x,
    const float* __restrict__ attr,
    const void* __restrict__ ei,
    const float* __restrict__ kW_unused)
{
    __nv_bfloat16* ksm  = reinterpret_cast<__nv_bfloat16*>(dsm_raw); // [192][PAD]
    __nv_bfloat16* atr  = ksm + ETILE * PAD;                          // [192][PADA]
    __nv_bfloat16* wsh  = atr + ETILE * PADA;                         // [64][PAD]
    int* ssrc = reinterpret_cast<int*>(wsh + ADIM * PAD);             // [192]
    int* stgt = ssrc + ETILE;                                         // [192]

    const int tid  = threadIdx.x;
    const int lane = tid & 31;
    const int wid  = tid >> 5;
    const int is64 = g_is64;
    const long long* ei64 = (const long long*)ei;
    const int*       ei32 = (const int*)ei;

    // Stage W (bf16) once per block
    {
        const uint4* g = reinterpret_cast<const uint4*>(g_Wkb);
        for (int idx = tid; idx < ADIM * FDIM / 8; idx += 384) {   // 1024 uint4
            int kr = idx >> 4, c8 = idx & 15;
            *reinterpret_cast<uint4*>(wsh + kr * PAD + c8 * 8) = g[idx];
        }
    }

    const uint32_t a_b = smem_u32(atr);
    const uint32_t w_b = smem_u32(wsh);

    const int ntiles = N_EDGES / ETILE;   // 3125 exact

    for (int tile = blockIdx.x; tile < ntiles; tile += gridDim.x) {
        const int e0 = tile * ETILE;
        __syncthreads();   // W staged (first iter) / prev-tile consumers done

        // Stage edge indices
        if (tid < ETILE)
            ssrc[tid] = is64 ? (int)ei64[e0 + tid] : ei32[e0 + tid];
        else {
            int t = tid - ETILE;
            stgt[t] = is64 ? (int)ei64[N_EDGES + e0 + t] : ei32[N_EDGES + e0 + t];
        }

        // Stage attr fp32 -> bf16: 192*32 float2 pairs = 6144
        #pragma unroll
        for (int r = 0; r < 16; r++) {
            int idx = tid + 384 * r;
            int el = idx >> 5, a2 = idx & 31;
            float2 v = *reinterpret_cast<const float2*>(
                           attr + (size_t)(e0 + el) * ADIM + a2 * 2);
            *reinterpret_cast<uint32_t*>(atr + el * PADA + a2 * 2) =
                pack_bf16(v.x, v.y);
        }
        __syncthreads();

        // ---- GEMM: acc[16x128] = attr_tile[wid*16..] @ W ----
        float acc[16][4];
        #pragma unroll
        for (int i = 0; i < 16; i++)
            #pragma unroll
            for (int j = 0; j < 4; j++) acc[i][j] = 0.f;

        #pragma unroll
        for (int ks = 0; ks < 4; ks++) {
            int k0 = ks * 16;
            uint32_t a[4];
            ldsm_x4(a[0], a[1], a[2], a[3],
                    a_b + ((wid * 16 + (lane & 15)) * PADA + k0
                           + (lane >> 4) * 8) * 2);
            #pragma unroll
            for (int ip = 0; ip < 8; ip++) {
                uint32_t b[4];
                ldsm_x4_t(b[0], b[1], b[2], b[3],
                          w_b + ((k0 + (lane & 15)) * PAD + ip * 16
                                 + (lane >> 4) * 8) * 2);
                mma16816(acc[2 * ip],     a, b);
                mma16816(acc[2 * ip + 1], a, b + 2);
            }
        }

        // ---- re-layout fragments to ksm (own rows only) ----
        {
            int rg = wid * 16 + (lane >> 2);
            int c0 = (lane & 3) * 2;
            #pragma unroll
            for (int i = 0; i < 16; i++) {
                *reinterpret_cast<uint32_t*>(ksm + rg * PAD + i * 8 + c0) =
                    pack_bf16(acc[i][0], acc[i][1]);
                *reinterpret_cast<uint32_t*>(ksm + (rg + 8) * PAD + i * 8 + c0) =
                    pack_bf16(acc[i][2], acc[i][3]);
            }
        }
        __syncwarp();

        // ---- scatter: g_h[tgt] += K[e] * x[src] ----
        #pragma unroll 4
        for (int e = 0; e < 16; e++) {
            int er  = wid * 16 + e;
            int src = ssrc[er];
            int tgt = stgt[er];
            uint2 kv = *reinterpret_cast<const uint2*>(ksm + er * PAD + lane * 4);
            float2 p0 = __bfloat1622float2(*reinterpret_cast<__nv_bfloat162*>(&kv.x));
            float2 p1 = __bfloat1622float2(*reinterpret_cast<__nv_bfloat162*>(&kv.y));
            float4 xv = __ldg(reinterpret_cast<const float4*>(
                                  x + (size_t)src * FDIM) + lane);
            float m0 = p0.x * xv.x;
            float m1 = p0.y * xv.y;
            float m2 = p1.x * xv.z;
            float m3 = p1.y * xv.w;
            float* dst = g_h + (size_t)tgt * FDIM + lane * 4;
            asm volatile("red.global.add.v4.f32 [%0], {%1,%2,%3,%4};"
                         :: "l"(dst), "f"(m0), "f"(m1), "f"(m2), "f"(m3)
                         : "memory");
        }
    }
}

// ---------------------------------------------------------------------------
// Tensor-core MLP: LN(fp32) -> bf16 mma GEMM1 -> GELU -> bf16 mma GEMM2 ->
// layer_scale + residual.
// ---------------------------------------------------------------------------
__global__ __launch_bounds__(256) void k_mlp(
    const float* __restrict__ x,
    const float* __restrict__ cb,
    const float* __restrict__ gamma,
    const float* __restrict__ beta,
    const float* __restrict__ b1,
    const float* __restrict__ b2,
    const float* __restrict__ ls,
    float* __restrict__ out)
{
    __nv_bfloat16* htile = reinterpret_cast<__nv_bfloat16*>(dsm_raw);  // [64][PAD]
    __nv_bfloat16* hid   = htile + 64 * PAD;                           // [64][PAD]
    __nv_bfloat16* wst   = htile + 128 * PAD;                          // [128][PAD]

    const int tid  = threadIdx.x;
    const int lane = tid & 31;
    const int wid  = tid >> 5;
    const int row0 = blockIdx.x * 64;
    const int wr   = wid & 3;
    const int wc   = wid >> 2;

    #pragma unroll
    for (int rr = 0; rr < 8; rr++) {
        int m = wid * 8 + rr;
        int row = row0 + m;
        if (row < N_NODES) {
            float v[4];
            #pragma unroll
            for (int q = 0; q < 4; q++)
                v[q] = g_h[(size_t)row * FDIM + lane + 32 * q]
                       + __ldg(cb + lane + 32 * q);
            float s1 = v[0] + v[1] + v[2] + v[3];
            float s2 = v[0]*v[0] + v[1]*v[1] + v[2]*v[2] + v[3]*v[3];
            #pragma unroll
            for (int o = 16; o > 0; o >>= 1) {
                s1 += __shfl_xor_sync(0xffffffffu, s1, o);
                s2 += __shfl_xor_sync(0xffffffffu, s2, o);
            }
            float mu   = s1 * (1.0f / 128.0f);
            float var  = s2 * (1.0f / 128.0f) - mu * mu;
            float rstd = rsqrtf(var + 1e-5f);
            #pragma unroll
            for (int q = 0; q < 4; q++) {
                float g = __ldg(gamma + lane + 32 * q);
                float b = __ldg(beta  + lane + 32 * q);
                htile[m * PAD + lane + 32 * q] =
                    __float2bfloat16((v[q] - mu) * rstd * g + b);
            }
        } else {
            #pragma unroll
            for (int q = 0; q < 4; q++)
                htile[m * PAD + lane + 32 * q] = __float2bfloat16(0.f);
        }
    }

    const uint32_t ht_b  = smem_u32(htile);
    const uint32_t hid_b = smem_u32(hid);
    const uint32_t w_b   = smem_u32(wst);

    float oacc[8][4];
    #pragma unroll
    for (int i = 0; i < 8; i++)
        #pragma unroll
        for (int j = 0; j < 4; j++) oacc[i][j] = 0.f;

    for (int jc = 0; jc < 4; jc++) {
        __syncthreads();
        {
            const uint4* g = reinterpret_cast<const uint4*>(g_W1b);
            #pragma unroll
            for (int r8 = 0; r8 < 8; r8++) {
                int idx = tid + 256 * r8;
                int krow = idx >> 4, c8 = idx & 15;
                *reinterpret_cast<uint4*>(wst + krow * PAD + c8 * 8) =
                    g[krow * 64 + jc * 16 + c8];
            }
        }
        __syncthreads();

        float g1[8][4];
        #pragma unroll
        for (int i = 0; i < 8; i++)
            #pragma unroll
            for (int j = 0; j < 4; j++) g1[i][j] = 0.f;

        #pragma unroll
        for (int ks = 0; ks < 8; ks++) {
            int k0 = ks * 16;
            uint32_t a[4];
            ldsm_x4(a[0], a[1], a[2], a[3],
                    ht_b + ((wr * 16 + (lane & 15)) * PAD + k0 + (lane >> 4) * 8) * 2);
            #pragma unroll
            for (int ip = 0; ip < 4; ip++) {
                uint32_t b[4];
                ldsm_x4_t(b[0], b[1], b[2], b[3],
                          w_b + ((k0 + (lane & 15)) * PAD + wc * 64 + ip * 16
                                 + (lane >> 4) * 8) * 2);
                mma16816(g1[2 * ip],     a, b);
                mma16816(g1[2 * ip + 1], a, b + 2);
            }
        }

        {
            int rg = wr * 16 + (lane >> 2);
            #pragma unroll
            for (int i = 0; i < 8; i++) {
                int coln = wc * 64 + i * 8 + (lane & 3) * 2;
                float2 bv = __ldg(reinterpret_cast<const float2*>(
                                      b1 + jc * 128 + coln));
                uint32_t p0 = pack_bf16(gelu_exact(g1[i][0] + bv.x),
                                        gelu_exact(g1[i][1] + bv.y));
                uint32_t p1 = pack_bf16(gelu_exact(g1[i][2] + bv.x),
                                        gelu_exact(g1[i][3] + bv.y));
                *reinterpret_cast<uint32_t*>(hid + rg * PAD + coln) = p0;
                *reinterpret_cast<uint32_t*>(hid + (rg + 8) * PAD + coln) = p1;
            }
        }
        __syncthreads();

        {
            const uint4* g = reinterpret_cast<const uint4*>(g_W2b);
            #pragma unroll
            for (int r8 = 0; r8 < 8; r8++) {
                int idx = tid + 256 * r8;
                int krow = idx >> 4, c8 = idx & 15;
                *reinterpret_cast<uint4*>(wst + krow * PAD + c8 * 8) =
                    g[(jc * 128 + krow) * 16 + c8];
            }
        }
        __syncthreads();

        #pragma unroll
        for (int ks = 0; ks < 8; ks++) {
            int k0 = ks * 16;
            uint32_t a[4];
            ldsm_x4(a[0], a[1], a[2], a[3],
                    hid_b + ((wr * 16 + (lane & 15)) * PAD + k0 + (lane >> 4) * 8) * 2);
            #pragma unroll
            for (int ip = 0; ip < 4; ip++) {
                uint32_t b[4];
                ldsm_x4_t(b[0], b[1], b[2], b[3],
                          w_b + ((k0 + (lane & 15)) * PAD + wc * 64 + ip * 16
                                 + (lane >> 4) * 8) * 2);
                mma16816(oacc[2 * ip],     a, b);
                mma16816(oacc[2 * ip + 1], a, b + 2);
            }
        }
    }

    {
        int rg = row0 + wr * 16 + (lane >> 2);
        #pragma unroll
        for (int i = 0; i < 8; i++) {
            int coln = wc * 64 + i * 8 + (lane & 3) * 2;
            float2 b2v = __ldg(reinterpret_cast<const float2*>(b2 + coln));
            float2 lsv = __ldg(reinterpret_cast<const float2*>(ls + coln));
            if (rg < N_NODES) {
                float2 xv = *reinterpret_cast<const float2*>(
                                x + (size_t)rg * FDIM + coln);
                float2 o;
                o.x = xv.x + lsv.x * (oacc[i][0] + b2v.x);
                o.y = xv.y + lsv.y * (oacc[i][1] + b2v.y);
                *reinterpret_cast<float2*>(out + (size_t)rg * FDIM + coln) = o;
            }
            if (rg + 8 < N_NODES) {
                float2 xv = *reinterpret_cast<const float2*>(
                                x + (size_t)(rg + 8) * FDIM + coln);
                float2 o;
                o.x = xv.x + lsv.x * (oacc[i][2] + b2v.x);
                o.y = xv.y + lsv.y * (oacc[i][3] + b2v.y);
                *reinterpret_cast<float2*>(out + (size_t)(rg + 8) * FDIM + coln) = o;
            }
        }
    }
}

// ---------------------------------------------------------------------------
extern "C" void kernel_launch(void* const* d_in, const int* in_sizes, int n_in,
                              void* d_out, int out_size)
{
    const float* x     = (const float*)d_in[0];
    const float* attr  = (const float*)d_in[1];
    const void*  ei    = d_in[2];
    const float* kW    = (const float*)d_in[4];
    const float* cb    = (const float*)d_in[5];
    const float* gamma = (const float*)d_in[6];
    const float* beta  = (const float*)d_in[7];
    const float* W1    = (const float*)d_in[8];
    const float* b1    = (const float*)d_in[9];
    const float* W2    = (const float*)d_in[10];
    const float* b2    = (const float*)d_in[11];
    const float* ls    = (const float*)d_in[12];
    float*       out   = (float*)d_out;

    const int edge_smem = (ETILE * PAD + ETILE * PADA + ADIM * PAD) * 2
                          + ETILE * 2 * (int)sizeof(int);               // 98816
    const int mlp_smem  = (128 * PAD + 128 * PAD) * 2;                   // 69632
    cudaFuncSetAttribute(k_edge, cudaFuncAttributeMaxDynamicSharedMemorySize, edge_smem);
    cudaFuncSetAttribute(k_mlp,  cudaFuncAttributeMaxDynamicSharedMemorySize, mlp_smem);

    k_probe<<<1, 1>>>(ei);
    k_zero<<<1024, 256>>>();
    k_cvt<<<544, 256>>>(W1, W2, kW);
    k_edge<<<148, 384, edge_smem>>>(x, attr, ei, kW);
    k_mlp<<<(N_NODES + 63) / 64, 256, mlp_smem>>>(x, cb, gamma, beta,
                                                  b1, b2, ls, out);
}

// round 7
// speedup vs baseline: 2.7494x; 1.0258x over previous
#include <cuda_runtime.h>
#include <cuda_bf16.h>
#include <cstdint>
#include <cstddef>

#define N_NODES 50000
#define N_EDGES 600000
#define FDIM    128
#define ADIM    64
#define HID     512
#define PAD     136   // bf16 row stride (272B) for 128-wide tiles
#define PADA    72    // bf16 row stride (144B) for 64-wide attr tiles
#define ETILE   64    // edges per tile: 600000/64 = 9375 exact

// Scratch
__device__ float g_h[(size_t)N_NODES * FDIM];
__device__ __nv_bfloat16 g_W1b[FDIM * HID];
__device__ __nv_bfloat16 g_W2b[HID * FDIM];
__device__ __nv_bfloat16 g_Wkb[ADIM * FDIM];
__device__ int g_is64;

// ---------------------------------------------------------------------------
// Zero scratch + probe edge_index dtype (block 0 / thread 0).
// ---------------------------------------------------------------------------
__global__ void k_zero(const void* ei) {
    if (blockIdx.x == 0 && threadIdx.x == 0) {
        const long long* p = (const long long*)ei;
        int ok = 1;
        #pragma unroll
        for (int i = 0; i < 8; i++) {
            long long v = p[i];
            if (v < 0 || v >= N_NODES) ok = 0;
        }
        g_is64 = ok;
    }
    float4* p4 = reinterpret_cast<float4*>(g_h);
    const int n4 = N_NODES * FDIM / 4;
    float4 z = make_float4(0.f, 0.f, 0.f, 0.f);
    for (int i = blockIdx.x * blockDim.x + threadIdx.x; i < n4;
         i += gridDim.x * blockDim.x)
        p4[i] = z;
}

// Convert W1, W2, kernel_W to bf16. 544*256 = 139264 = 65536+65536+8192 exact.
__global__ void k_cvt(const float* __restrict__ W1, const float* __restrict__ W2,
                      const float* __restrict__ kW) {
    int i = blockIdx.x * 256 + threadIdx.x;
    if (i < FDIM * HID)          g_W1b[i] = __float2bfloat16(W1[i]);
    else if (i < 2 * FDIM * HID) g_W2b[i - FDIM * HID] = __float2bfloat16(W2[i - FDIM * HID]);
    else                         g_Wkb[i - 2 * FDIM * HID] = __float2bfloat16(kW[i - 2 * FDIM * HID]);
}

// ---------------------------------------------------------------------------
// mma helpers
// ---------------------------------------------------------------------------
__device__ __forceinline__ uint32_t smem_u32(const void* p) {
    return (uint32_t)__cvta_generic_to_shared(p);
}
__device__ __forceinline__ void ldsm_x4(uint32_t& r0, uint32_t& r1,
                                        uint32_t& r2, uint32_t& r3, uint32_t a) {
    asm volatile("ldmatrix.sync.aligned.m8n8.x4.shared.b16 {%0,%1,%2,%3}, [%4];"
                 : "=r"(r0), "=r"(r1), "=r"(r2), "=r"(r3) : "r"(a));
}
__device__ __forceinline__ void ldsm_x4_t(uint32_t& r0, uint32_t& r1,
                                          uint32_t& r2, uint32_t& r3, uint32_t a) {
    asm volatile("ldmatrix.sync.aligned.m8n8.x4.trans.shared.b16 {%0,%1,%2,%3}, [%4];"
                 : "=r"(r0), "=r"(r1), "=r"(r2), "=r"(r3) : "r"(a));
}
__device__ __forceinline__ void mma16816(float* d, const uint32_t* a,
                                         const uint32_t* b) {
    asm volatile(
        "mma.sync.aligned.m16n8k16.row.col.f32.bf16.bf16.f32 "
        "{%0,%1,%2,%3}, {%4,%5,%6,%7}, {%8,%9}, {%0,%1,%2,%3};"
        : "+f"(d[0]), "+f"(d[1]), "+f"(d[2]), "+f"(d[3])
        : "r"(a[0]), "r"(a[1]), "r"(a[2]), "r"(a[3]), "r"(b[0]), "r"(b[1]));
}
__device__ __forceinline__ uint32_t pack_bf16(float lo, float hi) {
    return ((uint32_t)__bfloat16_as_ushort(__float2bfloat16(hi)) << 16) |
            (uint32_t)__bfloat16_as_ushort(__float2bfloat16(lo));
}
__device__ __forceinline__ float gelu_exact(float v) {
    return 0.5f * v * (1.0f + erff(v * 0.70710678118654752f));
}

extern __shared__ __align__(16) char dsm_raw[];

// ---------------------------------------------------------------------------
// Edge kernel v3: 64-edge tiles, block=256 (8 warps as 4 row-groups x 2
// col-halves), register prefetch of next tile's attr+indices, warp-local
// relayout + RED.v2 scatter. 2 CTAs/SM.
// ---------------------------------------------------------------------------
__global__ __launch_bounds__(256, 2) void k_edge(
    const float* __restrict__ x,
    const float* __restrict__ attr,
    const void* __restrict__ ei)
{
    __nv_bfloat16* ksm = reinterpret_cast<__nv_bfloat16*>(dsm_raw); // [64][PAD]
    __nv_bfloat16* atr = ksm + ETILE * PAD;                          // [64][PADA]
    __nv_bfloat16* wsh = atr + ETILE * PADA;                         // [64][PAD]
    int* ssrc = reinterpret_cast<int*>(wsh + ADIM * PAD);            // [64]
    int* stgt = ssrc + ETILE;                                        // [64]

    const int tid  = threadIdx.x;
    const int lane = tid & 31;
    const int wid  = tid >> 5;
    const int wr   = wid & 3;      // row group (16 edges)
    const int wc   = wid >> 2;     // col half (64 cols)
    const int is64 = g_is64;
    const long long* ei64 = (const long long*)ei;
    const int*       ei32 = (const int*)ei;

    // Stage W (bf16) once per block
    {
        const uint4* g = reinterpret_cast<const uint4*>(g_Wkb);
        for (int idx = tid; idx < ADIM * FDIM / 8; idx += 256) {   // 1024 uint4
            int kr = idx >> 4, c8 = idx & 15;
            *reinterpret_cast<uint4*>(wsh + kr * PAD + c8 * 8) = g[idx];
        }
    }

    const uint32_t a_b = smem_u32(atr);
    const uint32_t w_b = smem_u32(wsh);
    const int ntiles = N_EDGES / ETILE;   // 9375 exact

    int tile = blockIdx.x;
    int pidx = 0;
    float2 pf[8];

    // Prologue: prefetch first tile
    {
        const int e0 = tile * ETILE;
        if (tid < ETILE)
            pidx = is64 ? (int)ei64[e0 + tid] : ei32[e0 + tid];
        else if (tid < 2 * ETILE)
            pidx = is64 ? (int)ei64[N_EDGES + e0 + tid - ETILE]
                        : ei32[N_EDGES + e0 + tid - ETILE];
        #pragma unroll
        for (int r = 0; r < 8; r++) {
            int idx = tid + 256 * r;           // 0..2047 float2 slots
            int el = idx >> 5, a2 = idx & 31;
            pf[r] = *reinterpret_cast<const float2*>(
                        attr + (size_t)(e0 + el) * ADIM + a2 * 2);
        }
    }

    for (; tile < ntiles; tile += gridDim.x) {
        // ---- commit prefetched tile to smem ----
        if (tid < ETILE)           ssrc[tid] = pidx;
        else if (tid < 2 * ETILE)  stgt[tid - ETILE] = pidx;
        #pragma unroll
        for (int r = 0; r < 8; r++) {
            int idx = tid + 256 * r;
            int el = idx >> 5, a2 = idx & 31;
            *reinterpret_cast<uint32_t*>(atr + el * PADA + a2 * 2) =
                pack_bf16(pf[r].x, pf[r].y);
        }
        __syncthreads();

        // ---- prefetch next tile (overlaps mma + scatter) ----
        {
            int nt = tile + gridDim.x;
            if (nt < ntiles) {
                const int e0n = nt * ETILE;
                if (tid < ETILE)
                    pidx = is64 ? (int)ei64[e0n + tid] : ei32[e0n + tid];
                else if (tid < 2 * ETILE)
                    pidx = is64 ? (int)ei64[N_EDGES + e0n + tid - ETILE]
                                : ei32[N_EDGES + e0n + tid - ETILE];
                #pragma unroll
                for (int r = 0; r < 8; r++) {
                    int idx = tid + 256 * r;
                    int el = idx >> 5, a2 = idx & 31;
                    pf[r] = *reinterpret_cast<const float2*>(
                                attr + (size_t)(e0n + el) * ADIM + a2 * 2);
                }
            }
        }

        // ---- GEMM: acc[16x64] = attr_rows[wr] @ W[:, wc*64:+64] ----
        float acc[8][4];
        #pragma unroll
        for (int i = 0; i < 8; i++)
            #pragma unroll
            for (int j = 0; j < 4; j++) acc[i][j] = 0.f;

        #pragma unroll
        for (int ks = 0; ks < 4; ks++) {
            int k0 = ks * 16;
            uint32_t a[4];
            ldsm_x4(a[0], a[1], a[2], a[3],
                    a_b + ((wr * 16 + (lane & 15)) * PADA + k0
                           + (lane >> 4) * 8) * 2);
            #pragma unroll
            for (int ip = 0; ip < 4; ip++) {
                uint32_t b[4];
                ldsm_x4_t(b[0], b[1], b[2], b[3],
                          w_b + ((k0 + (lane & 15)) * PAD + wc * 64 + ip * 16
                                 + (lane >> 4) * 8) * 2);
                mma16816(acc[2 * ip],     a, b);
                mma16816(acc[2 * ip + 1], a, b + 2);
            }
        }

        // ---- warp-local relayout to ksm ----
        {
            int rg = wr * 16 + (lane >> 2);
            int c0 = wc * 64 + (lane & 3) * 2;
            #pragma unroll
            for (int i = 0; i < 8; i++) {
                *reinterpret_cast<uint32_t*>(ksm + rg * PAD + c0 + i * 8) =
                    pack_bf16(acc[i][0], acc[i][1]);
                *reinterpret_cast<uint32_t*>(ksm + (rg + 8) * PAD + c0 + i * 8) =
                    pack_bf16(acc[i][2], acc[i][3]);
            }
        }
        __syncwarp();

        // ---- warp-local scatter: 16 edges x own 64-col half, RED.v2 ----
        #pragma unroll 4
        for (int e = 0; e < 16; e++) {
            int er  = wr * 16 + e;
            int src = ssrc[er];
            int tgt = stgt[er];
            uint32_t kv = *reinterpret_cast<const uint32_t*>(
                              ksm + er * PAD + wc * 64 + lane * 2);
            float2 p = __bfloat1622float2(
                           *reinterpret_cast<__nv_bfloat162*>(&kv));
            float2 xv = __ldg(reinterpret_cast<const float2*>(
                                  x + (size_t)src * FDIM + wc * 64 + lane * 2));
            float m0 = p.x * xv.x;
            float m1 = p.y * xv.y;
            float* dst = g_h + (size_t)tgt * FDIM + wc * 64 + lane * 2;
            asm volatile("red.global.add.v2.f32 [%0], {%1,%2};"
                         :: "l"(dst), "f"(m0), "f"(m1) : "memory");
        }
        __syncthreads();   // protect atr/ssrc/ksm before next tile's STS
    }
}

// ---------------------------------------------------------------------------
// Tensor-core MLP (unchanged): LN(fp32) -> bf16 mma GEMM1 -> GELU ->
// bf16 mma GEMM2 -> layer_scale + residual.
// ---------------------------------------------------------------------------
__global__ __launch_bounds__(256) void k_mlp(
    const float* __restrict__ x,
    const float* __restrict__ cb,
    const float* __restrict__ gamma,
    const float* __restrict__ beta,
    const float* __restrict__ b1,
    const float* __restrict__ b2,
    const float* __restrict__ ls,
    float* __restrict__ out)
{
    __nv_bfloat16* htile = reinterpret_cast<__nv_bfloat16*>(dsm_raw);  // [64][PAD]
    __nv_bfloat16* hid   = htile + 64 * PAD;                           // [64][PAD]
    __nv_bfloat16* wst   = htile + 128 * PAD;                          // [128][PAD]

    const int tid  = threadIdx.x;
    const int lane = tid & 31;
    const int wid  = tid >> 5;
    const int row0 = blockIdx.x * 64;
    const int wr   = wid & 3;
    const int wc   = wid >> 2;

    #pragma unroll
    for (int rr = 0; rr < 8; rr++) {
        int m = wid * 8 + rr;
        int row = row0 + m;
        if (row < N_NODES) {
            float v[4];
            #pragma unroll
            for (int q = 0; q < 4; q++)
                v[q] = g_h[(size_t)row * FDIM + lane + 32 * q]
                       + __ldg(cb + lane + 32 * q);
            float s1 = v[0] + v[1] + v[2] + v[3];
            float s2 = v[0]*v[0] + v[1]*v[1] + v[2]*v[2] + v[3]*v[3];
            #pragma unroll
            for (int o = 16; o > 0; o >>= 1) {
                s1 += __shfl_xor_sync(0xffffffffu, s1, o);
                s2 += __shfl_xor_sync(0xffffffffu, s2, o);
            }
            float mu   = s1 * (1.0f / 128.0f);
            float var  = s2 * (1.0f / 128.0f) - mu * mu;
            float rstd = rsqrtf(var + 1e-5f);
            #pragma unroll
            for (int q = 0; q < 4; q++) {
                float g = __ldg(gamma + lane + 32 * q);
                float b = __ldg(beta  + lane + 32 * q);
                htile[m * PAD + lane + 32 * q] =
                    __float2bfloat16((v[q] - mu) * rstd * g + b);
            }
        } else {
            #pragma unroll
            for (int q = 0; q < 4; q++)
                htile[m * PAD + lane + 32 * q] = __float2bfloat16(0.f);
        }
    }

    const uint32_t ht_b  = smem_u32(htile);
    const uint32_t hid_b = smem_u32(hid);
    const uint32_t w_b   = smem_u32(wst);

    float oacc[8][4];
    #pragma unroll
    for (int i = 0; i < 8; i++)
        #pragma unroll
        for (int j = 0; j < 4; j++) oacc[i][j] = 0.f;

    for (int jc = 0; jc < 4; jc++) {
        __syncthreads();
        {
            const uint4* g = reinterpret_cast<const uint4*>(g_W1b);
            #pragma unroll
            for (int r8 = 0; r8 < 8; r8++) {
                int idx = tid + 256 * r8;
                int krow = idx >> 4, c8 = idx & 15;
                *reinterpret_cast<uint4*>(wst + krow * PAD + c8 * 8) =
                    g[krow * 64 + jc * 16 + c8];
            }
        }
        __syncthreads();

        float g1[8][4];
        #pragma unroll
        for (int i = 0; i < 8; i++)
            #pragma unroll
            for (int j = 0; j < 4; j++) g1[i][j] = 0.f;

        #pragma unroll
        for (int ks = 0; ks < 8; ks++) {
            int k0 = ks * 16;
            uint32_t a[4];
            ldsm_x4(a[0], a[1], a[2], a[3],
                    ht_b + ((wr * 16 + (lane & 15)) * PAD + k0 + (lane >> 4) * 8) * 2);
            #pragma unroll
            for (int ip = 0; ip < 4; ip++) {
                uint32_t b[4];
                ldsm_x4_t(b[0], b[1], b[2], b[3],
                          w_b + ((k0 + (lane & 15)) * PAD + wc * 64 + ip * 16
                                 + (lane >> 4) * 8) * 2);
                mma16816(g1[2 * ip],     a, b);
                mma16816(g1[2 * ip + 1], a, b + 2);
            }
        }

        {
            int rg = wr * 16 + (lane >> 2);
            #pragma unroll
            for (int i = 0; i < 8; i++) {
                int coln = wc * 64 + i * 8 + (lane & 3) * 2;
                float2 bv = __ldg(reinterpret_cast<const float2*>(
                                      b1 + jc * 128 + coln));
                uint32_t p0 = pack_bf16(gelu_exact(g1[i][0] + bv.x),
                                        gelu_exact(g1[i][1] + bv.y));
                uint32_t p1 = pack_bf16(gelu_exact(g1[i][2] + bv.x),
                                        gelu_exact(g1[i][3] + bv.y));
                *reinterpret_cast<uint32_t*>(hid + rg * PAD + coln) = p0;
                *reinterpret_cast<uint32_t*>(hid + (rg + 8) * PAD + coln) = p1;
            }
        }
        __syncthreads();

        {
            const uint4* g = reinterpret_cast<const uint4*>(g_W2b);
            #pragma unroll
            for (int r8 = 0; r8 < 8; r8++) {
                int idx = tid + 256 * r8;
                int krow = idx >> 4, c8 = idx & 15;
                *reinterpret_cast<uint4*>(wst + krow * PAD + c8 * 8) =
                    g[(jc * 128 + krow) * 16 + c8];
            }
        }
        __syncthreads();

        #pragma unroll
        for (int ks = 0; ks < 8; ks++) {
            int k0 = ks * 16;
            uint32_t a[4];
            ldsm_x4(a[0], a[1], a[2], a[3],
                    hid_b + ((wr * 16 + (lane & 15)) * PAD + k0 + (lane >> 4) * 8) * 2);
            #pragma unroll
            for (int ip = 0; ip < 4; ip++) {
                uint32_t b[4];
                ldsm_x4_t(b[0], b[1], b[2], b[3],
                          w_b + ((k0 + (lane & 15)) * PAD + wc * 64 + ip * 16
                                 + (lane >> 4) * 8) * 2);
                mma16816(oacc[2 * ip],     a, b);
                mma16816(oacc[2 * ip + 1], a, b + 2);
            }
        }
    }

    {
        int rg = row0 + wr * 16 + (lane >> 2);
        #pragma unroll
        for (int i = 0; i < 8; i++) {
            int coln = wc * 64 + i * 8 + (lane & 3) * 2;
            float2 b2v = __ldg(reinterpret_cast<const float2*>(b2 + coln));
            float2 lsv = __ldg(reinterpret_cast<const float2*>(ls + coln));
            if (rg < N_NODES) {
                float2 xv = *reinterpret_cast<const float2*>(
                                x + (size_t)rg * FDIM + coln);
                float2 o;
                o.x = xv.x + lsv.x * (oacc[i][0] + b2v.x);
                o.y = xv.y + lsv.y * (oacc[i][1] + b2v.y);
                *reinterpret_cast<float2*>(out + (size_t)rg * FDIM + coln) = o;
            }
            if (rg + 8 < N_NODES) {
                float2 xv = *reinterpret_cast<const float2*>(
                                x + (size_t)(rg + 8) * FDIM + coln);
                float2 o;
                o.x = xv.x + lsv.x * (oacc[i][2] + b2v.x);
                o.y = xv.y + lsv.y * (oacc[i][3] + b2v.y);
                *reinterpret_cast<float2*>(out + (size_t)(rg + 8) * FDIM + coln) = o;
            }
        }
    }
}

// ---------------------------------------------------------------------------
extern "C" void kernel_launch(void* const* d_in, const int* in_sizes, int n_in,
                              void* d_out, int out_size)
{
    const float* x     = (const float*)d_in[0];
    const float* attr  = (const float*)d_in[1];
    const void*  ei    = d_in[2];
    const float* kW    = (const float*)d_in[4];
    const float* cb    = (const float*)d_in[5];
    const float* gamma = (const float*)d_in[6];
    const float* beta  = (const float*)d_in[7];
    const float* W1    = (const float*)d_in[8];
    const float* b1    = (const float*)d_in[9];
    const float* W2    = (const float*)d_in[10];
    const float* b2    = (const float*)d_in[11];
    const float* ls    = (const float*)d_in[12];
    float*       out   = (float*)d_out;

    const int edge_smem = (ETILE * PAD + ETILE * PADA + ADIM * PAD) * 2
                          + ETILE * 2 * (int)sizeof(int);               // 44544
    const int mlp_smem  = (128 * PAD + 128 * PAD) * 2;                   // 69632
    cudaFuncSetAttribute(k_edge, cudaFuncAttributeMaxDynamicSharedMemorySize, edge_smem);
    cudaFuncSetAttribute(k_mlp,  cudaFuncAttributeMaxDynamicSharedMemorySize, mlp_smem);

    k_zero<<<1024, 256>>>(ei);
    k_cvt<<<544, 256>>>(W1, W2, kW);
    k_edge<<<296, 256, edge_smem>>>(x, attr, ei);
    k_mlp<<<(N_NODES + 63) / 64, 256, mlp_smem>>>(x, cb, gamma, beta,
                                                  b1, b2, ls, out);
}

// round 10
// speedup vs baseline: 3.0470x; 1.1082x over previous
#include <cuda_runtime.h>
#include <cuda_bf16.h>
#include <cstdint>
#include <cstddef>

#define N_NODES 50000
#define N_EDGES 600000
#define FDIM    128
#define ADIM    64
#define HID     512
#define PAD     136   // bf16 row stride (272B)
#define PADA    72    // bf16 row stride (144B) for 64-wide attr tiles
#define ETILE   64    // edges per tile: 600000/64 = 9375 exact

// Scratch
__device__ float g_h[(size_t)N_NODES * FDIM];
__device__ __nv_bfloat16 g_W1b[FDIM * HID];
__device__ __nv_bfloat16 g_W2b[HID * FDIM];
__device__ __nv_bfloat16 g_Wkb[ADIM * FDIM];
__device__ int g_is64;

// ---------------------------------------------------------------------------
__global__ void k_zero(const void* ei) {
    if (blockIdx.x == 0 && threadIdx.x == 0) {
        const long long* p = (const long long*)ei;
        int ok = 1;
        #pragma unroll
        for (int i = 0; i < 8; i++) {
            long long v = p[i];
            if (v < 0 || v >= N_NODES) ok = 0;
        }
        g_is64 = ok;
    }
    float4* p4 = reinterpret_cast<float4*>(g_h);
    const int n4 = N_NODES * FDIM / 4;
    float4 z = make_float4(0.f, 0.f, 0.f, 0.f);
    for (int i = blockIdx.x * blockDim.x + threadIdx.x; i < n4;
         i += gridDim.x * blockDim.x)
        p4[i] = z;
}

__global__ void k_cvt(const float* __restrict__ W1, const float* __restrict__ W2,
                      const float* __restrict__ kW) {
    int i = blockIdx.x * 256 + threadIdx.x;
    if (i < FDIM * HID)          g_W1b[i] = __float2bfloat16(W1[i]);
    else if (i < 2 * FDIM * HID) g_W2b[i - FDIM * HID] = __float2bfloat16(W2[i - FDIM * HID]);
    else                         g_Wkb[i - 2 * FDIM * HID] = __float2bfloat16(kW[i - 2 * FDIM * HID]);
}

// ---------------------------------------------------------------------------
// helpers
// ---------------------------------------------------------------------------
__device__ __forceinline__ uint32_t smem_u32(const void* p) {
    return (uint32_t)__cvta_generic_to_shared(p);
}
__device__ __forceinline__ void cp_async16(uint32_t dst, const void* src) {
    asm volatile("cp.async.cg.shared.global [%0], [%1], 16;" :: "r"(dst), "l"(src));
}
__device__ __forceinline__ void cp_async8(uint32_t dst, const void* src) {
    asm volatile("cp.async.ca.shared.global [%0], [%1], 8;" :: "r"(dst), "l"(src));
}
#define CP_COMMIT()   asm volatile("cp.async.commit_group;" ::: "memory")
#define CP_WAIT_ALL() asm volatile("cp.async.wait_group 0;" ::: "memory")

__device__ __forceinline__ void ldsm_x4(uint32_t& r0, uint32_t& r1,
                                        uint32_t& r2, uint32_t& r3, uint32_t a) {
    asm volatile("ldmatrix.sync.aligned.m8n8.x4.shared.b16 {%0,%1,%2,%3}, [%4];"
                 : "=r"(r0), "=r"(r1), "=r"(r2), "=r"(r3) : "r"(a));
}
__device__ __forceinline__ void ldsm_x4_t(uint32_t& r0, uint32_t& r1,
                                          uint32_t& r2, uint32_t& r3, uint32_t a) {
    asm volatile("ldmatrix.sync.aligned.m8n8.x4.trans.shared.b16 {%0,%1,%2,%3}, [%4];"
                 : "=r"(r0), "=r"(r1), "=r"(r2), "=r"(r3) : "r"(a));
}
__device__ __forceinline__ void mma16816(float* d, const uint32_t* a,
                                         const uint32_t* b) {
    asm volatile(
        "mma.sync.aligned.m16n8k16.row.col.f32.bf16.bf16.f32 "
        "{%0,%1,%2,%3}, {%4,%5,%6,%7}, {%8,%9}, {%0,%1,%2,%3};"
        : "+f"(d[0]), "+f"(d[1]), "+f"(d[2]), "+f"(d[3])
        : "r"(a[0]), "r"(a[1]), "r"(a[2]), "r"(a[3]), "r"(b[0]), "r"(b[1]));
}
__device__ __forceinline__ uint32_t pack_bf16(float lo, float hi) {
    return ((uint32_t)__bfloat16_as_ushort(__float2bfloat16(hi)) << 16) |
            (uint32_t)__bfloat16_as_ushort(__float2bfloat16(lo));
}
__device__ __forceinline__ float gelu_exact(float v) {
    return 0.5f * v * (1.0f + erff(v * 0.70710678118654752f));
}

extern __shared__ __align__(16) char dsm_raw[];

// ---------------------------------------------------------------------------
// Edge kernel v4: 64-edge tiles, 8 warps (4 row-groups x 2 col-halves),
// register prefetch of next tile attr/idx, cp.async prefetch of x-gather
// into smem overlapping the mma, warp-local RED.v2 scatter. 2 CTAs/SM.
// ---------------------------------------------------------------------------
__global__ __launch_bounds__(256, 2) void k_edge(
    const float* __restrict__ x,
    const float* __restrict__ attr,
    const void* __restrict__ ei)
{
    __nv_bfloat16* ksm = reinterpret_cast<__nv_bfloat16*>(dsm_raw); // [64][PAD]
    __nv_bfloat16* atr = ksm + ETILE * PAD;                          // [64][PADA]
    __nv_bfloat16* wsh = atr + ETILE * PADA;                         // [64][PAD]
    int* ssrc = reinterpret_cast<int*>(wsh + ADIM * PAD);            // [64]
    int* stgt = ssrc + ETILE;                                        // [64]
    float* xbuf = reinterpret_cast<float*>(stgt + ETILE);            // [64][128]

    const int tid  = threadIdx.x;
    const int lane = tid & 31;
    const int wid  = tid >> 5;
    const int wr   = wid & 3;      // row group (16 edges)
    const int wc   = wid >> 2;     // col half (64 cols)
    const int is64 = g_is64;
    const long long* ei64 = (const long long*)ei;
    const int*       ei32 = (const int*)ei;

    // Stage W (bf16) once per block
    {
        const uint4* g = reinterpret_cast<const uint4*>(g_Wkb);
        for (int idx = tid; idx < ADIM * FDIM / 8; idx += 256) {
            int kr = idx >> 4, c8 = idx & 15;
            *reinterpret_cast<uint4*>(wsh + kr * PAD + c8 * 8) = g[idx];
        }
    }

    const uint32_t a_b  = smem_u32(atr);
    const uint32_t w_b  = smem_u32(wsh);
    const uint32_t xb_b = smem_u32(xbuf);
    const int ntiles = N_EDGES / ETILE;   // 9375 exact

    int tile = blockIdx.x;
    int pidx = 0;
    float2 pf[8];

    // Prologue: prefetch first tile into registers
    {
        const int e0 = tile * ETILE;
        if (tid < ETILE)
            pidx = is64 ? (int)ei64[e0 + tid] : ei32[e0 + tid];
        else if (tid < 2 * ETILE)
            pidx = is64 ? (int)ei64[N_EDGES + e0 + tid - ETILE]
                        : ei32[N_EDGES + e0 + tid - ETILE];
        #pragma unroll
        for (int r = 0; r < 8; r++) {
            int idx = tid + 256 * r;
            int el = idx >> 5, a2 = idx & 31;
            pf[r] = *reinterpret_cast<const float2*>(
                        attr + (size_t)(e0 + el) * ADIM + a2 * 2);
        }
    }

    for (; tile < ntiles; tile += gridDim.x) {
        // ---- commit prefetched tile to smem ----
        if (tid < ETILE)           ssrc[tid] = pidx;
        else if (tid < 2 * ETILE)  stgt[tid - ETILE] = pidx;
        #pragma unroll
        for (int r = 0; r < 8; r++) {
            int idx = tid + 256 * r;
            int el = idx >> 5, a2 = idx & 31;
            *reinterpret_cast<uint32_t*>(atr + el * PADA + a2 * 2) =
                pack_bf16(pf[r].x, pf[r].y);
        }
        __syncthreads();

        // ---- issue x-gather cp.async (overlaps GEMM); warp-local slots ----
        #pragma unroll
        for (int e = 0; e < 16; e++) {
            int er  = wr * 16 + e;
            int src = ssrc[er];
            cp_async8(xb_b + (er * 128 + wc * 64 + lane * 2) * 4,
                      x + (size_t)src * FDIM + wc * 64 + lane * 2);
        }
        CP_COMMIT();

        // ---- prefetch next tile attr/idx into registers ----
        {
            int nt = tile + gridDim.x;
            if (nt < ntiles) {
                const int e0n = nt * ETILE;
                if (tid < ETILE)
                    pidx = is64 ? (int)ei64[e0n + tid] : ei32[e0n + tid];
                else if (tid < 2 * ETILE)
                    pidx = is64 ? (int)ei64[N_EDGES + e0n + tid - ETILE]
                                : ei32[N_EDGES + e0n + tid - ETILE];
                #pragma unroll
                for (int r = 0; r < 8; r++) {
                    int idx = tid + 256 * r;
                    int el = idx >> 5, a2 = idx & 31;
                    pf[r] = *reinterpret_cast<const float2*>(
                                attr + (size_t)(e0n + el) * ADIM + a2 * 2);
                }
            }
        }

        // ---- GEMM: acc[16x64] = attr_rows[wr] @ W[:, wc*64:+64] ----
        float acc[8][4];
        #pragma unroll
        for (int i = 0; i < 8; i++)
            #pragma unroll
            for (int j = 0; j < 4; j++) acc[i][j] = 0.f;

        #pragma unroll
        for (int ks = 0; ks < 4; ks++) {
            int k0 = ks * 16;
            uint32_t a[4];
            ldsm_x4(a[0], a[1], a[2], a[3],
                    a_b + ((wr * 16 + (lane & 15)) * PADA + k0
                           + (lane >> 4) * 8) * 2);
            #pragma unroll
            for (int ip = 0; ip < 4; ip++) {
                uint32_t b[4];
                ldsm_x4_t(b[0], b[1], b[2], b[3],
                          w_b + ((k0 + (lane & 15)) * PAD + wc * 64 + ip * 16
                                 + (lane >> 4) * 8) * 2);
                mma16816(acc[2 * ip],     a, b);
                mma16816(acc[2 * ip + 1], a, b + 2);
            }
        }

        // ---- warp-local relayout to ksm ----
        {
            int rg = wr * 16 + (lane >> 2);
            int c0 = wc * 64 + (lane & 3) * 2;
            #pragma unroll
            for (int i = 0; i < 8; i++) {
                *reinterpret_cast<uint32_t*>(ksm + rg * PAD + c0 + i * 8) =
                    pack_bf16(acc[i][0], acc[i][1]);
                *reinterpret_cast<uint32_t*>(ksm + (rg + 8) * PAD + c0 + i * 8) =
                    pack_bf16(acc[i][2], acc[i][3]);
            }
        }
        __syncwarp();
        CP_WAIT_ALL();   // own x slots ready (thread reads what it issued)

        // ---- warp-local scatter: 16 edges x own 64-col half, RED.v2 ----
        #pragma unroll 4
        for (int e = 0; e < 16; e++) {
            int er  = wr * 16 + e;
            int tgt = stgt[er];
            uint32_t kv = *reinterpret_cast<const uint32_t*>(
                              ksm + er * PAD + wc * 64 + lane * 2);
            float2 p = __bfloat1622float2(
                           *reinterpret_cast<__nv_bfloat162*>(&kv));
            float2 xv = *reinterpret_cast<const float2*>(
                            xbuf + er * 128 + wc * 64 + lane * 2);
            float m0 = p.x * xv.x;
            float m1 = p.y * xv.y;
            float* dst = g_h + (size_t)tgt * FDIM + wc * 64 + lane * 2;
            asm volatile("red.global.add.v2.f32 [%0], {%1,%2};"
                         :: "l"(dst), "f"(m0), "f"(m1) : "memory");
        }
        __syncthreads();   // protect atr/ssrc/ksm/xbuf before next tile
    }
}

// ---------------------------------------------------------------------------
// Tensor-core MLP v2: cp.async double-buffered weight staging.
// LN(fp32) -> bf16 mma GEMM1 -> GELU -> bf16 mma GEMM2 -> scale + residual.
// ---------------------------------------------------------------------------
__global__ __launch_bounds__(256, 2) void k_mlp(
    const float* __restrict__ x,
    const float* __restrict__ cb,
    const float* __restrict__ gamma,
    const float* __restrict__ beta,
    const float* __restrict__ b1,
    const float* __restrict__ b2,
    const float* __restrict__ ls,
    float* __restrict__ out)
{
    __nv_bfloat16* htile = reinterpret_cast<__nv_bfloat16*>(dsm_raw);  // [64][PAD]
    __nv_bfloat16* hid   = htile + 64 * PAD;                           // [64][PAD]
    __nv_bfloat16* wstA  = htile + 128 * PAD;                          // [128][PAD]
    __nv_bfloat16* wstB  = wstA + 128 * PAD;                           // [128][PAD]

    const int tid  = threadIdx.x;
    const int lane = tid & 31;
    const int wid  = tid >> 5;
    const int row0 = blockIdx.x * 64;
    const int wr   = wid & 3;
    const int wc   = wid >> 2;

    const uint32_t wA_b = smem_u32(wstA);
    const uint32_t wB_b = smem_u32(wstB);

    // Prologue: async-stage W1 chunk 0 -> A (overlaps LN)
    {
        #pragma unroll
        for (int r8 = 0; r8 < 8; r8++) {
            int idx = tid + 256 * r8;
            int krow = idx >> 4, c8 = idx & 15;
            cp_async16(wA_b + (krow * PAD + c8 * 8) * 2,
                       g_W1b + krow * HID + c8 * 8);
        }
        CP_COMMIT();
    }

    // ---- LayerNorm (fp32) -> bf16 htile ----
    #pragma unroll
    for (int rr = 0; rr < 8; rr++) {
        int m = wid * 8 + rr;
        int row = row0 + m;
        if (row < N_NODES) {
            float v[4];
            #pragma unroll
            for (int q = 0; q < 4; q++)
                v[q] = g_h[(size_t)row * FDIM + lane + 32 * q]
                       + __ldg(cb + lane + 32 * q);
            float s1 = v[0] + v[1] + v[2] + v[3];
            float s2 = v[0]*v[0] + v[1]*v[1] + v[2]*v[2] + v[3]*v[3];
            #pragma unroll
            for (int o = 16; o > 0; o >>= 1) {
                s1 += __shfl_xor_sync(0xffffffffu, s1, o);
                s2 += __shfl_xor_sync(0xffffffffu, s2, o);
            }
            float mu   = s1 * (1.0f / 128.0f);
            float var  = s2 * (1.0f / 128.0f) - mu * mu;
            float rstd = rsqrtf(var + 1e-5f);
            #pragma unroll
            for (int q = 0; q < 4; q++) {
                float g = __ldg(gamma + lane + 32 * q);
                float b = __ldg(beta  + lane + 32 * q);
                htile[m * PAD + lane + 32 * q] =
                    __float2bfloat16((v[q] - mu) * rstd * g + b);
            }
        } else {
            #pragma unroll
            for (int q = 0; q < 4; q++)
                htile[m * PAD + lane + 32 * q] = __float2bfloat16(0.f);
        }
    }

    const uint32_t ht_b  = smem_u32(htile);
    const uint32_t hid_b = smem_u32(hid);

    float oacc[8][4];
    #pragma unroll
    for (int i = 0; i < 8; i++)
        #pragma unroll
        for (int j = 0; j < 4; j++) oacc[i][j] = 0.f;

    for (int jc = 0; jc < 4; jc++) {
        CP_WAIT_ALL();
        __syncthreads();   // A (W1 chunk jc) ready; htile visible; B consumers done

        // prefetch W2 chunk jc -> B (overlaps GEMM1)
        {
            #pragma unroll
            for (int r8 = 0; r8 < 8; r8++) {
                int idx = tid + 256 * r8;
                int krow = idx >> 4, c8 = idx & 15;
                cp_async16(wB_b + (krow * PAD + c8 * 8) * 2,
                           g_W2b + (size_t)(jc * 128 + krow) * FDIM + c8 * 8);
            }
            CP_COMMIT();
        }

        // ---- GEMM1: g1[16x64] = htile[wr] @ W1chunk[:, wc*64:+64] ----
        float g1[8][4];
        #pragma unroll
        for (int i = 0; i < 8; i++)
            #pragma unroll
            for (int j = 0; j < 4; j++) g1[i][j] = 0.f;

        #pragma unroll
        for (int ks = 0; ks < 8; ks++) {
            int k0 = ks * 16;
            uint32_t a[4];
            ldsm_x4(a[0], a[1], a[2], a[3],
                    ht_b + ((wr * 16 + (lane & 15)) * PAD + k0 + (lane >> 4) * 8) * 2);
            #pragma unroll
            for (int ip = 0; ip < 4; ip++) {
                uint32_t b[4];
                ldsm_x4_t(b[0], b[1], b[2], b[3],
                          wA_b + ((k0 + (lane & 15)) * PAD + wc * 64 + ip * 16
                                  + (lane >> 4) * 8) * 2);
                mma16816(g1[2 * ip],     a, b);
                mma16816(g1[2 * ip + 1], a, b + 2);
            }
        }

        // ---- bias + GELU -> bf16 hid ----
        {
            int rg = wr * 16 + (lane >> 2);
            #pragma unroll
            for (int i = 0; i < 8; i++) {
                int coln = wc * 64 + i * 8 + (lane & 3) * 2;
                float2 bv = __ldg(reinterpret_cast<const float2*>(
                                      b1 + jc * 128 + coln));
                uint32_t p0 = pack_bf16(gelu_exact(g1[i][0] + bv.x),
                                        gelu_exact(g1[i][1] + bv.y));
                uint32_t p1 = pack_bf16(gelu_exact(g1[i][2] + bv.x),
                                        gelu_exact(g1[i][3] + bv.y));
                *reinterpret_cast<uint32_t*>(hid + rg * PAD + coln) = p0;
                *reinterpret_cast<uint32_t*>(hid + (rg + 8) * PAD + coln) = p1;
            }
        }
        CP_WAIT_ALL();
        __syncthreads();   // B (W2 chunk jc) ready; hid visible; A consumers done

        // prefetch W1 chunk jc+1 -> A (overlaps GEMM2)
        if (jc < 3) {
            #pragma unroll
            for (int r8 = 0; r8 < 8; r8++) {
                int idx = tid + 256 * r8;
                int krow = idx >> 4, c8 = idx & 15;
                cp_async16(wA_b + (krow * PAD + c8 * 8) * 2,
                           g_W1b + krow * HID + (jc + 1) * 128 + c8 * 8);
            }
            CP_COMMIT();
        }

        // ---- GEMM2: oacc += hid[wr] @ W2chunk[:, wc*64:+64] ----
        #pragma unroll
        for (int ks = 0; ks < 8; ks++) {
            int k0 = ks * 16;
            uint32_t a[4];
            ldsm_x4(a[0], a[1], a[2], a[3],
                    hid_b + ((wr * 16 + (lane & 15)) * PAD + k0 + (lane >> 4) * 8) * 2);
            #pragma unroll
            for (int ip = 0; ip < 4; ip++) {
                uint32_t b[4];
                ldsm_x4_t(b[0], b[1], b[2], b[3],
                          wB_b + ((k0 + (lane & 15)) * PAD + wc * 64 + ip * 16
                                  + (lane >> 4) * 8) * 2);
                mma16816(oacc[2 * ip],     a, b);
                mma16816(oacc[2 * ip + 1], a, b + 2);
            }
        }
    }

    // ---- epilogue: out = x + ls * (oacc + b2) ----
    {
        int rg = row0 + wr * 16 + (lane >> 2);
        #pragma unroll
        for (int i = 0; i < 8; i++) {
            int coln = wc * 64 + i * 8 + (lane & 3) * 2;
            float2 b2v = __ldg(reinterpret_cast<const float2*>(b2 + coln));
            float2 lsv = __ldg(reinterpret_cast<const float2*>(ls + coln));
            if (rg < N_NODES) {
                float2 xv = *reinterpret_cast<const float2*>(
                                x + (size_t)rg * FDIM + coln);
                float2 o;
                o.x = xv.x + lsv.x * (oacc[i][0] + b2v.x);
                o.y = xv.y + lsv.y * (oacc[i][1] + b2v.y);
                *reinterpret_cast<float2*>(out + (size_t)rg * FDIM + coln) = o;
            }
            if (rg + 8 < N_NODES) {
                float2 xv = *reinterpret_cast<const float2*>(
                                x + (size_t)(rg + 8) * FDIM + coln);
                float2 o;
                o.x = xv.x + lsv.x * (oacc[i][2] + b2v.x);
                o.y = xv.y + lsv.y * (oacc[i][3] + b2v.y);
                *reinterpret_cast<float2*>(out + (size_t)(rg + 8) * FDIM + coln) = o;
            }
        }
    }
}

// ---------------------------------------------------------------------------
extern "C" void kernel_launch(void* const* d_in, const int* in_sizes, int n_in,
                              void* d_out, int out_size)
{
    const float* x     = (const float*)d_in[0];
    const float* attr  = (const float*)d_in[1];
    const void*  ei    = d_in[2];
    const float* kW    = (const float*)d_in[4];
    const float* cb    = (const float*)d_in[5];
    const float* gamma = (const float*)d_in[6];
    const float* beta  = (const float*)d_in[7];
    const float* W1    = (const float*)d_in[8];
    const float* b1    = (const float*)d_in[9];
    const float* W2    = (const float*)d_in[10];
    const float* b2    = (const float*)d_in[11];
    const float* ls    = (const float*)d_in[12];
    float*       out   = (float*)d_out;

    const int edge_smem = (ETILE * PAD + ETILE * PADA + ADIM * PAD) * 2
                          + ETILE * 2 * (int)sizeof(int)
                          + ETILE * FDIM * (int)sizeof(float);          // 77312
    const int mlp_smem  = (64 * PAD + 64 * PAD + 256 * PAD) * 2;        // 104448
    cudaFuncSetAttribute(k_edge, cudaFuncAttributeMaxDynamicSharedMemorySize, edge_smem);
    cudaFuncSetAttribute(k_mlp,  cudaFuncAttributeMaxDynamicSharedMemorySize, mlp_smem);

    k_zero<<<1024, 256>>>(ei);
    k_cvt<<<544, 256>>>(W1, W2, kW);
    k_edge<<<296, 256, edge_smem>>>(x, attr, ei);
    k_mlp<<<(N_NODES + 63) / 64, 256, mlp_smem>>>(x, cb, gamma, beta,
                                                  b1, b2, ls, out);
}